// round 2
// baseline (speedup 1.0000x reference)
#include <cuda_runtime.h>

#define N_NODES 4096
#define EMB 10
#define NBATCH 64
#define CI 64
#define CO 64

#define BM 128
#define BN 128
#define BK 16

// Scratch (allocation-free rule: __device__ globals)
__device__ float g_A[(size_t)N_NODES * N_NODES];          // softmax(relu(E E^T))
__device__ float g_y1[(size_t)NBATCH * N_NODES * CI];     // diffusion result, layout [b][n][c]

// ---------------------------------------------------------------------------
// Kernel 1: per-row softmax of relu(E E^T).  One CTA per row n, 256 threads,
// each thread holds 16 of the 4096 row entries in registers.
// ---------------------------------------------------------------------------
__global__ __launch_bounds__(256) void k_softmax(const float* __restrict__ E) {
    const int n = blockIdx.x;
    const int tid = threadIdx.x;
    __shared__ float s_e[EMB];
    __shared__ float s_red[8];

    if (tid < EMB) s_e[tid] = E[n * EMB + tid];
    __syncthreads();
    float er[EMB];
#pragma unroll
    for (int d = 0; d < EMB; d++) er[d] = s_e[d];

    float vals[16];
    float vmax = 0.f;  // relu >= 0
#pragma unroll
    for (int j = 0; j < 16; j++) {
        const int m = tid + j * 256;
        const float* em = E + m * EMB;
        float dot = 0.f;
#pragma unroll
        for (int d = 0; d < EMB; d++) dot = fmaf(er[d], __ldg(em + d), dot);
        dot = fmaxf(dot, 0.f);
        vals[j] = dot;
        vmax = fmaxf(vmax, dot);
    }
    // block-reduce max
#pragma unroll
    for (int o = 16; o; o >>= 1) vmax = fmaxf(vmax, __shfl_xor_sync(0xffffffffu, vmax, o));
    if ((tid & 31) == 0) s_red[tid >> 5] = vmax;
    __syncthreads();
    vmax = s_red[0];
#pragma unroll
    for (int w = 1; w < 8; w++) vmax = fmaxf(vmax, s_red[w]);

    float ssum = 0.f;
#pragma unroll
    for (int j = 0; j < 16; j++) {
        vals[j] = __expf(vals[j] - vmax);
        ssum += vals[j];
    }
#pragma unroll
    for (int o = 16; o; o >>= 1) ssum += __shfl_xor_sync(0xffffffffu, ssum, o);
    __syncthreads();
    if ((tid & 31) == 0) s_red[tid >> 5] = ssum;
    __syncthreads();
    ssum = 0.f;
#pragma unroll
    for (int w = 0; w < 8; w++) ssum += s_red[w];
    const float inv = 1.0f / ssum;

#pragma unroll
    for (int j = 0; j < 16; j++)
        g_A[(size_t)n * N_NODES + tid + j * 256] = vals[j] * inv;
}

// ---------------------------------------------------------------------------
// Kernel 2: y1 = A @ X, where X[m, b*64+c] = x[b, m, c].
// Classic 128x128x16 double-buffered SGEMM, 256 threads, 8x8 thread tile
// split into 4+4 halves for conflict-free LDS.128.
// Output written directly in [b][n][c] layout.
// ---------------------------------------------------------------------------
__global__ __launch_bounds__(256, 2) void k_diffuse(const float* __restrict__ x) {
    __shared__ float As[2][BK][BM + 4];
    __shared__ float Bs[2][BK][BN];

    const int tid = threadIdx.x;
    const int row0 = blockIdx.y * BM;
    const int col0 = blockIdx.x * BN;
    const int tx = tid & 15;   // 16 col groups
    const int ty = tid >> 4;   // 16 row groups

    // load index precompute
    int a_m[2], a_q[2], b_k[2], b_j[2];
#pragma unroll
    for (int u = 0; u < 2; u++) {
        const int idx = tid + u * 256;
        a_m[u] = idx >> 2;          // 0..127 (row within A tile)
        a_q[u] = idx & 3;           // float4 group along k
        b_k[u] = idx >> 5;          // 0..15 (k within tile)
        b_j[u] = (idx & 31) * 4;    // col within tile
    }

    float4 ra[2], rb[2];
    float acc[8][8];
#pragma unroll
    for (int i = 0; i < 8; i++)
#pragma unroll
        for (int j = 0; j < 8; j++) acc[i][j] = 0.f;

    // ---- prologue: load tile kk=0 ----
#pragma unroll
    for (int u = 0; u < 2; u++) {
        ra[u] = *(const float4*)&g_A[(size_t)(row0 + a_m[u]) * N_NODES + a_q[u] * 4];
        const int j = col0 + b_j[u];
        const int bb = j >> 6, cc = j & 63;
        rb[u] = *(const float4*)&x[((size_t)bb * N_NODES + b_k[u]) * CI + cc];
    }
#pragma unroll
    for (int u = 0; u < 2; u++) {
        As[0][a_q[u] * 4 + 0][a_m[u]] = ra[u].x;
        As[0][a_q[u] * 4 + 1][a_m[u]] = ra[u].y;
        As[0][a_q[u] * 4 + 2][a_m[u]] = ra[u].z;
        As[0][a_q[u] * 4 + 3][a_m[u]] = ra[u].w;
        *(float4*)&Bs[0][b_k[u]][b_j[u]] = rb[u];
    }

    const int NT = N_NODES / BK;  // 256
    for (int t = 0; t < NT; t++) {
        __syncthreads();
        const int cur = t & 1;
        const int kk_next = (t + 1) * BK;
        if (t + 1 < NT) {
#pragma unroll
            for (int u = 0; u < 2; u++) {
                ra[u] = *(const float4*)&g_A[(size_t)(row0 + a_m[u]) * N_NODES + kk_next + a_q[u] * 4];
                const int j = col0 + b_j[u];
                const int bb = j >> 6, cc = j & 63;
                rb[u] = *(const float4*)&x[((size_t)bb * N_NODES + kk_next + b_k[u]) * CI + cc];
            }
        }
#pragma unroll
        for (int k = 0; k < BK; k++) {
            const float4 a0 = *(const float4*)&As[cur][k][ty * 4];
            const float4 a1 = *(const float4*)&As[cur][k][64 + ty * 4];
            const float4 b0 = *(const float4*)&Bs[cur][k][tx * 4];
            const float4 b1 = *(const float4*)&Bs[cur][k][64 + tx * 4];
            const float ar[8] = {a0.x, a0.y, a0.z, a0.w, a1.x, a1.y, a1.z, a1.w};
            const float br[8] = {b0.x, b0.y, b0.z, b0.w, b1.x, b1.y, b1.z, b1.w};
#pragma unroll
            for (int i = 0; i < 8; i++)
#pragma unroll
                for (int j = 0; j < 8; j++)
                    acc[i][j] = fmaf(ar[i], br[j], acc[i][j]);
        }
        if (t + 1 < NT) {
            const int nxt = cur ^ 1;
#pragma unroll
            for (int u = 0; u < 2; u++) {
                As[nxt][a_q[u] * 4 + 0][a_m[u]] = ra[u].x;
                As[nxt][a_q[u] * 4 + 1][a_m[u]] = ra[u].y;
                As[nxt][a_q[u] * 4 + 2][a_m[u]] = ra[u].z;
                As[nxt][a_q[u] * 4 + 3][a_m[u]] = ra[u].w;
                *(float4*)&Bs[nxt][b_k[u]][b_j[u]] = rb[u];
            }
        }
    }

    // epilogue: write y1 in [b][n][c] layout
#pragma unroll
    for (int ih = 0; ih < 2; ih++) {
#pragma unroll
        for (int i = 0; i < 4; i++) {
            const int r = row0 + ih * 64 + ty * 4 + i;
#pragma unroll
            for (int jh = 0; jh < 2; jh++) {
                const int j = col0 + jh * 64 + tx * 4;
                const int bb = j >> 6, cc = j & 63;
                float4 v;
                v.x = acc[ih * 4 + i][jh * 4 + 0];
                v.y = acc[ih * 4 + i][jh * 4 + 1];
                v.z = acc[ih * 4 + i][jh * 4 + 2];
                v.w = acc[ih * 4 + i][jh * 4 + 3];
                *(float4*)&g_y1[((size_t)bb * N_NODES + r) * CI + cc] = v;
            }
        }
    }
}

// ---------------------------------------------------------------------------
// Kernel 3: per-node weights from pools + final per-node GEMM.
// out[b,n,o] = sum_i x[b,n,i]*W0[n,i,o] + y1[b,n,i]*W1[n,i,o] + bias[n,o]
// One CTA per node; W (2x64x64) generated once into smem, reused by 64 batches.
// ---------------------------------------------------------------------------
__global__ __launch_bounds__(256) void k_out(const float* __restrict__ E,
                                             const float* __restrict__ Wp,
                                             const float* __restrict__ bp,
                                             const float* __restrict__ x,
                                             float* __restrict__ out) {
    const int n = blockIdx.x;
    const int tid = threadIdx.x;
    __shared__ float sW[2][64][64];  // [k][i][o]  32KB
    __shared__ float sb[64];
    __shared__ float se[EMB];
    __shared__ float sx[16][64];
    __shared__ float sy[16][64];

    if (tid < EMB) se[tid] = E[n * EMB + tid];
    __syncthreads();
    float e[EMB];
#pragma unroll
    for (int d = 0; d < EMB; d++) e[d] = se[d];

    // W[k,i,o] = sum_d e[d] * Wp[d,k,i,o];  Wp stride over d = 2*64*64 = 8192
#pragma unroll 8
    for (int u = 0; u < 32; u++) {
        const int idx = tid + u * 256;  // k*4096 + i*64 + o
        float acc = 0.f;
#pragma unroll
        for (int d = 0; d < EMB; d++) acc = fmaf(e[d], __ldg(Wp + d * 8192 + idx), acc);
        ((float*)sW)[idx] = acc;
    }
    if (tid < 64) {
        float acc = 0.f;
#pragma unroll
        for (int d = 0; d < EMB; d++) acc = fmaf(e[d], bp[d * 64 + tid], acc);
        sb[tid] = acc;
    }
    __syncthreads();

    const int og = tid & 15;  // o group: 4 outputs
    const int bl = tid >> 4;  // batch lane within 16-batch slab

    for (int b0 = 0; b0 < NBATCH; b0 += 16) {
#pragma unroll
        for (int u = 0; u < 4; u++) {
            const int idx = tid + u * 256;  // b*64 + c
            const int bb = idx >> 6, cc = idx & 63;
            sx[bb][cc] = x[((size_t)(b0 + bb) * N_NODES + n) * CI + cc];
            sy[bb][cc] = g_y1[((size_t)(b0 + bb) * N_NODES + n) * CI + cc];
        }
        __syncthreads();

        float4 acc;
        acc.x = sb[og * 4 + 0];
        acc.y = sb[og * 4 + 1];
        acc.z = sb[og * 4 + 2];
        acc.w = sb[og * 4 + 3];
#pragma unroll
        for (int i = 0; i < 64; i++) {
            const float4 w0 = *(const float4*)&sW[0][i][og * 4];
            const float4 w1 = *(const float4*)&sW[1][i][og * 4];
            const float xv = sx[bl][i];
            const float yv = sy[bl][i];
            acc.x = fmaf(xv, w0.x, fmaf(yv, w1.x, acc.x));
            acc.y = fmaf(xv, w0.y, fmaf(yv, w1.y, acc.y));
            acc.z = fmaf(xv, w0.z, fmaf(yv, w1.z, acc.z));
            acc.w = fmaf(xv, w0.w, fmaf(yv, w1.w, acc.w));
        }
        *(float4*)&out[((size_t)(b0 + bl) * N_NODES + n) * CO + og * 4] = acc;
        __syncthreads();
    }
}

// ---------------------------------------------------------------------------
extern "C" void kernel_launch(void* const* d_in, const int* in_sizes, int n_in,
                              void* d_out, int out_size) {
    const float* x  = (const float*)d_in[0];   // [64,4096,64]
    const float* E  = (const float*)d_in[1];   // [4096,10]
    const float* Wp = (const float*)d_in[2];   // [10,2,64,64]
    const float* bp = (const float*)d_in[3];   // [10,64]
    float* out = (float*)d_out;                // [64,4096,64]

    k_softmax<<<N_NODES, 256>>>(E);
    dim3 grid(N_NODES / BN, N_NODES / BM);
    k_diffuse<<<grid, 256>>>(x);
    k_out<<<N_NODES, 256>>>(E, Wp, bp, x, out);
}

// round 4
// speedup vs baseline: 1.8067x; 1.8067x over previous
#include <cuda_runtime.h>
#include <cuda_bf16.h>
#include <cstdint>

#define N_NODES 4096
#define EMB 10
#define NBATCH 64
#define CI 64
#define CO 64

// ---------------- device scratch (allocation-free rule) --------------------
__device__ __nv_bfloat16 g_Ah[(size_t)N_NODES * N_NODES];   // softmax(relu(EE^T)) hi
__device__ __nv_bfloat16 g_Al[(size_t)N_NODES * N_NODES];   // lo residual
__device__ __nv_bfloat16 g_Xh[(size_t)N_NODES * N_NODES];   // X^T[j=b*64+c][m] hi
__device__ __nv_bfloat16 g_Xl[(size_t)N_NODES * N_NODES];   // lo
__device__ float g_y1[(size_t)NBATCH * N_NODES * CI];       // diffusion result [b][n][c]

// ---------------- PTX helpers ---------------------------------------------
__device__ __forceinline__ uint32_t smem_u32(const void* p) {
    uint32_t a;
    asm("{ .reg .u64 t; cvta.to.shared.u64 t, %1; cvt.u32.u64 %0, t; }" : "=r"(a) : "l"(p));
    return a;
}
__device__ __forceinline__ void cp_async16(uint32_t dst, const void* src) {
    asm volatile("cp.async.cg.shared.global [%0], [%1], 16;" :: "r"(dst), "l"(src));
}
#define CP_COMMIT()  asm volatile("cp.async.commit_group;" ::: "memory")
#define CP_WAIT(N)   asm volatile("cp.async.wait_group %0;" :: "n"(N) : "memory")

__device__ __forceinline__ void ldsm4(uint32_t* r, uint32_t addr) {
    asm volatile("ldmatrix.sync.aligned.m8n8.x4.shared.b16 {%0,%1,%2,%3}, [%4];"
        : "=r"(r[0]), "=r"(r[1]), "=r"(r[2]), "=r"(r[3]) : "r"(addr));
}
__device__ __forceinline__ void mma_bf16(float* c, const uint32_t* a,
                                         uint32_t b0, uint32_t b1) {
    asm volatile("mma.sync.aligned.m16n8k16.row.col.f32.bf16.bf16.f32 "
        "{%0,%1,%2,%3}, {%4,%5,%6,%7}, {%8,%9}, {%0,%1,%2,%3};"
        : "+f"(c[0]), "+f"(c[1]), "+f"(c[2]), "+f"(c[3])
        : "r"(a[0]), "r"(a[1]), "r"(a[2]), "r"(a[3]), "r"(b0), "r"(b1));
}

// ---------------------------------------------------------------------------
// Kernel 1: per-row softmax of relu(E E^T), output split bf16 hi/lo.
// ---------------------------------------------------------------------------
__global__ __launch_bounds__(256) void k_softmax(const float* __restrict__ E) {
    const int n = blockIdx.x;
    const int tid = threadIdx.x;
    __shared__ float s_e[EMB];
    __shared__ float s_red[8];

    if (tid < EMB) s_e[tid] = E[n * EMB + tid];
    __syncthreads();
    float er[EMB];
#pragma unroll
    for (int d = 0; d < EMB; d++) er[d] = s_e[d];

    float vals[16];
    float vmax = 0.f;
#pragma unroll
    for (int j = 0; j < 16; j++) {
        const int m = tid + j * 256;
        const float* em = E + m * EMB;
        float dot = 0.f;
#pragma unroll
        for (int d = 0; d < EMB; d++) dot = fmaf(er[d], __ldg(em + d), dot);
        dot = fmaxf(dot, 0.f);
        vals[j] = dot;
        vmax = fmaxf(vmax, dot);
    }
#pragma unroll
    for (int o = 16; o; o >>= 1) vmax = fmaxf(vmax, __shfl_xor_sync(0xffffffffu, vmax, o));
    if ((tid & 31) == 0) s_red[tid >> 5] = vmax;
    __syncthreads();
    vmax = s_red[0];
#pragma unroll
    for (int w = 1; w < 8; w++) vmax = fmaxf(vmax, s_red[w]);

    float ssum = 0.f;
#pragma unroll
    for (int j = 0; j < 16; j++) {
        vals[j] = __expf(vals[j] - vmax);
        ssum += vals[j];
    }
#pragma unroll
    for (int o = 16; o; o >>= 1) ssum += __shfl_xor_sync(0xffffffffu, ssum, o);
    __syncthreads();
    if ((tid & 31) == 0) s_red[tid >> 5] = ssum;
    __syncthreads();
    ssum = 0.f;
#pragma unroll
    for (int w = 0; w < 8; w++) ssum += s_red[w];
    const float inv = 1.0f / ssum;

#pragma unroll
    for (int j = 0; j < 16; j++) {
        const float v = vals[j] * inv;
        const __nv_bfloat16 h = __float2bfloat16(v);
        const float r = v - __bfloat162float(h);
        const size_t idx = (size_t)n * N_NODES + tid + j * 256;
        g_Ah[idx] = h;
        g_Al[idx] = __float2bfloat16(r);
    }
}

// ---------------------------------------------------------------------------
// Kernel 2: transpose x[b][m][c] -> X^T[j=b*64+c][m] as bf16 hi/lo.
// ---------------------------------------------------------------------------
__global__ __launch_bounds__(256) void k_transpose(const float* __restrict__ x) {
    const int b = blockIdx.y;
    const int m0 = blockIdx.x * 64;
    const int tid = threadIdx.x;
    __shared__ float tile[64][65];

#pragma unroll
    for (int i = 0; i < 16; i++) {
        const int idx = tid + i * 256;
        const int mi = idx >> 6, c = idx & 63;
        tile[mi][c] = x[((size_t)b * N_NODES + m0 + mi) * CI + c];
    }
    __syncthreads();
#pragma unroll
    for (int i = 0; i < 16; i++) {
        const int idx = tid + i * 256;
        const int c = idx >> 6, mm = idx & 63;
        const float v = tile[mm][c];
        const __nv_bfloat16 h = __float2bfloat16(v);
        const float r = v - __bfloat162float(h);
        const size_t o = (size_t)(b * 64 + c) * N_NODES + m0 + mm;
        g_Xh[o] = h;
        g_Xl[o] = __float2bfloat16(r);
    }
}

// ---------------------------------------------------------------------------
// Kernel 3: y1 = A @ X via mma.sync bf16 split-precision (legacy HMMA path;
// tcgen05 PTX is rejected by this build's compute_103 target).
// D[n, j] = Ah*Bh + Ah*Bl + Al*Bh  (fp32 accumulate, drop lo*lo)
// CTA tile 128x128, K-chunk 32, 2-stage cp.async, 8 warps (4Mx2N), warp 32x64.
// ---------------------------------------------------------------------------
#define KC 32
#define ROWB 80                       // padded row: 40 bf16 = 80B (conflict-free LDSM)
#define TILE_B (128 * ROWB)           // 10240 B
#define STAGE_B (4 * TILE_B)          // Ah, Al, Bh, Bl
#define SMEM_MMA (2 * STAGE_B)        // 81920 B
#define NT (N_NODES / KC)             // 128 chunks

__global__ __launch_bounds__(256, 2) void k_mma() {
    extern __shared__ __align__(128) char smem[];
    const uint32_t sb = smem_u32(smem);
    const int tid = threadIdx.x;
    const int wid = tid >> 5;
    const int lane = tid & 31;
    const int wm = wid >> 1;          // 0..3  (M: 32 rows each)
    const int wn = wid & 1;           // 0..1  (N: 64 cols each)
    const int n0 = blockIdx.y * 128;
    const int j0 = blockIdx.x * 128;

    // global load assignment: 2 segments of 16B per tile per thread
    int grow[2], gseg[2];
    uint32_t sdst[2];
#pragma unroll
    for (int i = 0; i < 2; i++) {
        const int s = tid + i * 256;      // 0..511
        grow[i] = s >> 2;                 // 0..127
        gseg[i] = s & 3;                  // 16B segment within 64B row
        sdst[i] = (uint32_t)(grow[i] * ROWB + gseg[i] * 16);
    }

    // ldmatrix source offsets (within a tile)
    uint32_t offA[2], offB[4];
#pragma unroll
    for (int mb = 0; mb < 2; mb++)
        offA[mb] = (uint32_t)((wm * 32 + mb * 16 + (lane & 15)) * ROWB + (lane >> 4) * 16);
#pragma unroll
    for (int nb = 0; nb < 4; nb++)
        offB[nb] = (uint32_t)((wn * 64 + nb * 16 + (lane & 15)) * ROWB + (lane >> 4) * 16);

    float acc[2][8][4];
#pragma unroll
    for (int mb = 0; mb < 2; mb++)
#pragma unroll
        for (int nb = 0; nb < 8; nb++)
#pragma unroll
            for (int q = 0; q < 4; q++) acc[mb][nb][q] = 0.f;

    // prologue: chunk 0 -> stage 0
    {
        const uint32_t st = sb;
#pragma unroll
        for (int i = 0; i < 2; i++) {
            const size_t ga = (size_t)(n0 + grow[i]) * N_NODES + gseg[i] * 8;
            const size_t gb = (size_t)(j0 + grow[i]) * N_NODES + gseg[i] * 8;
            cp_async16(st + 0 * TILE_B + sdst[i], g_Ah + ga);
            cp_async16(st + 1 * TILE_B + sdst[i], g_Al + ga);
            cp_async16(st + 2 * TILE_B + sdst[i], g_Xh + gb);
            cp_async16(st + 3 * TILE_B + sdst[i], g_Xl + gb);
        }
        CP_COMMIT();
    }

    for (int t = 0; t < NT; t++) {
        const int s = t & 1;
        if (t + 1 < NT) {
            const uint32_t st = sb + (s ^ 1) * STAGE_B;
            const int m0 = (t + 1) * KC;
#pragma unroll
            for (int i = 0; i < 2; i++) {
                const size_t ga = (size_t)(n0 + grow[i]) * N_NODES + m0 + gseg[i] * 8;
                const size_t gb = (size_t)(j0 + grow[i]) * N_NODES + m0 + gseg[i] * 8;
                cp_async16(st + 0 * TILE_B + sdst[i], g_Ah + ga);
                cp_async16(st + 1 * TILE_B + sdst[i], g_Al + ga);
                cp_async16(st + 2 * TILE_B + sdst[i], g_Xh + gb);
                cp_async16(st + 3 * TILE_B + sdst[i], g_Xl + gb);
            }
            CP_COMMIT();
            CP_WAIT(1);
        } else {
            CP_WAIT(0);
        }
        __syncthreads();

        const uint32_t st = sb + s * STAGE_B;
        const uint32_t bAh = st, bAl = st + TILE_B, bBh = st + 2 * TILE_B, bBl = st + 3 * TILE_B;
#pragma unroll
        for (int ks = 0; ks < 2; ks++) {
            const uint32_t ko = ks * 32;   // 16 bf16 = 32 bytes
            uint32_t ah[2][4], al[2][4];
#pragma unroll
            for (int mb = 0; mb < 2; mb++) {
                ldsm4(ah[mb], bAh + offA[mb] + ko);
                ldsm4(al[mb], bAl + offA[mb] + ko);
            }
#pragma unroll
            for (int nb = 0; nb < 4; nb++) {
                uint32_t bh[4], bl[4];
                ldsm4(bh, bBh + offB[nb] + ko);
                ldsm4(bl, bBl + offB[nb] + ko);
#pragma unroll
                for (int mb = 0; mb < 2; mb++) {
                    float* c0 = acc[mb][nb * 2 + 0];
                    float* c1 = acc[mb][nb * 2 + 1];
                    mma_bf16(c0, ah[mb], bh[0], bh[2]);
                    mma_bf16(c0, ah[mb], bl[0], bl[2]);
                    mma_bf16(c0, al[mb], bh[0], bh[2]);
                    mma_bf16(c1, ah[mb], bh[1], bh[3]);
                    mma_bf16(c1, ah[mb], bl[1], bl[3]);
                    mma_bf16(c1, al[mb], bh[1], bh[3]);
                }
            }
        }
        __syncthreads();
    }

    // epilogue: write y1[b][n][c]; each warp's 64-col span lies in ONE batch b.
    const int jw = j0 + wn * 64;
    const int b = jw >> 6;
#pragma unroll
    for (int mb = 0; mb < 2; mb++) {
        const int nrow = n0 + wm * 32 + mb * 16 + (lane >> 2);
#pragma unroll
        for (int nb = 0; nb < 8; nb++) {
            const int c = nb * 8 + (lane & 3) * 2;
            float* d0 = &g_y1[((size_t)b * N_NODES + nrow) * CI + c];
            float* d1 = &g_y1[((size_t)b * N_NODES + nrow + 8) * CI + c];
            float2 v0 = {acc[mb][nb][0], acc[mb][nb][1]};
            float2 v1 = {acc[mb][nb][2], acc[mb][nb][3]};
            *(float2*)d0 = v0;
            *(float2*)d1 = v1;
        }
    }
}

// ---------------------------------------------------------------------------
// Kernel 4: per-node weights + final per-node GEMM.
// ---------------------------------------------------------------------------
__global__ __launch_bounds__(256) void k_out(const float* __restrict__ E,
                                             const float* __restrict__ Wp,
                                             const float* __restrict__ bp,
                                             const float* __restrict__ x,
                                             float* __restrict__ out) {
    const int n = blockIdx.x;
    const int tid = threadIdx.x;
    __shared__ float sW[2][64][64];
    __shared__ float sb_[64];
    __shared__ float se[EMB];
    __shared__ float sx[16][64];
    __shared__ float sy[16][64];

    if (tid < EMB) se[tid] = E[n * EMB + tid];
    __syncthreads();
    float e[EMB];
#pragma unroll
    for (int d = 0; d < EMB; d++) e[d] = se[d];

#pragma unroll 8
    for (int u = 0; u < 32; u++) {
        const int idx = tid + u * 256;
        float acc = 0.f;
#pragma unroll
        for (int d = 0; d < EMB; d++) acc = fmaf(e[d], __ldg(Wp + d * 8192 + idx), acc);
        ((float*)sW)[idx] = acc;
    }
    if (tid < 64) {
        float acc = 0.f;
#pragma unroll
        for (int d = 0; d < EMB; d++) acc = fmaf(e[d], bp[d * 64 + tid], acc);
        sb_[tid] = acc;
    }
    __syncthreads();

    const int og = tid & 15;
    const int bl = tid >> 4;

    for (int b0 = 0; b0 < NBATCH; b0 += 16) {
#pragma unroll
        for (int u = 0; u < 4; u++) {
            const int idx = tid + u * 256;
            const int bb = idx >> 6, cc = idx & 63;
            sx[bb][cc] = x[((size_t)(b0 + bb) * N_NODES + n) * CI + cc];
            sy[bb][cc] = g_y1[((size_t)(b0 + bb) * N_NODES + n) * CI + cc];
        }
        __syncthreads();

        float4 acc;
        acc.x = sb_[og * 4 + 0];
        acc.y = sb_[og * 4 + 1];
        acc.z = sb_[og * 4 + 2];
        acc.w = sb_[og * 4 + 3];
#pragma unroll
        for (int i = 0; i < 64; i++) {
            const float4 w0 = *(const float4*)&sW[0][i][og * 4];
            const float4 w1 = *(const float4*)&sW[1][i][og * 4];
            const float xv = sx[bl][i];
            const float yv = sy[bl][i];
            acc.x = fmaf(xv, w0.x, fmaf(yv, w1.x, acc.x));
            acc.y = fmaf(xv, w0.y, fmaf(yv, w1.y, acc.y));
            acc.z = fmaf(xv, w0.z, fmaf(yv, w1.z, acc.z));
            acc.w = fmaf(xv, w0.w, fmaf(yv, w1.w, acc.w));
        }
        *(float4*)&out[((size_t)(b0 + bl) * N_NODES + n) * CO + og * 4] = acc;
        __syncthreads();
    }
}

// ---------------------------------------------------------------------------
extern "C" void kernel_launch(void* const* d_in, const int* in_sizes, int n_in,
                              void* d_out, int out_size) {
    const float* x  = (const float*)d_in[0];
    const float* E  = (const float*)d_in[1];
    const float* Wp = (const float*)d_in[2];
    const float* bp = (const float*)d_in[3];
    float* out = (float*)d_out;

    cudaFuncSetAttribute(k_mma, cudaFuncAttributeMaxDynamicSharedMemorySize, SMEM_MMA);

    k_softmax<<<N_NODES, 256>>>(E);
    dim3 gT(N_NODES / 64, NBATCH);
    k_transpose<<<gT, 256>>>(x);
    dim3 gM(N_NODES / 128, N_NODES / 128);
    k_mma<<<gM, 256, SMEM_MMA>>>();
    k_out<<<N_NODES, 256>>>(E, Wp, bp, x, out);
}

// round 5
// speedup vs baseline: 2.7221x; 1.5066x over previous
#include <cuda_runtime.h>
#include <cuda_fp16.h>
#include <cstdint>

#define N_NODES 4096
#define EMB 10
#define NBATCH 64
#define CI 64
#define CO 64

// ---------------- device scratch (allocation-free rule) --------------------
__device__ __half g_Ah[(size_t)N_NODES * N_NODES];   // softmax(relu(EE^T)) hi (fp16)
__device__ __half g_Al[(size_t)N_NODES * N_NODES];   // lo residual (fp16)
__device__ __half g_Xh[(size_t)N_NODES * N_NODES];   // X^T[j=b*64+c][m] (fp16)
__device__ float g_y1[(size_t)NBATCH * N_NODES * CI];// diffusion result [b][n][c]

// ---------------- PTX helpers ---------------------------------------------
__device__ __forceinline__ uint32_t smem_u32(const void* p) {
    uint32_t a;
    asm("{ .reg .u64 t; cvta.to.shared.u64 t, %1; cvt.u32.u64 %0, t; }" : "=r"(a) : "l"(p));
    return a;
}
__device__ __forceinline__ void cp_async16(uint32_t dst, const void* src) {
    asm volatile("cp.async.cg.shared.global [%0], [%1], 16;" :: "r"(dst), "l"(src));
}
#define CP_COMMIT()  asm volatile("cp.async.commit_group;" ::: "memory")
#define CP_WAIT(N)   asm volatile("cp.async.wait_group %0;" :: "n"(N) : "memory")

__device__ __forceinline__ void ldsm4(uint32_t* r, uint32_t addr) {
    asm volatile("ldmatrix.sync.aligned.m8n8.x4.shared.b16 {%0,%1,%2,%3}, [%4];"
        : "=r"(r[0]), "=r"(r[1]), "=r"(r[2]), "=r"(r[3]) : "r"(addr));
}
__device__ __forceinline__ void mma_f16(float* c, const uint32_t* a,
                                        uint32_t b0, uint32_t b1) {
    asm volatile("mma.sync.aligned.m16n8k16.row.col.f32.f16.f16.f32 "
        "{%0,%1,%2,%3}, {%4,%5,%6,%7}, {%8,%9}, {%0,%1,%2,%3};"
        : "+f"(c[0]), "+f"(c[1]), "+f"(c[2]), "+f"(c[3])
        : "r"(a[0]), "r"(a[1]), "r"(a[2]), "r"(a[3]), "r"(b0), "r"(b1));
}

// ---------------------------------------------------------------------------
// Kernel 1: per-row softmax of relu(E E^T), output split fp16 hi/lo.
// ---------------------------------------------------------------------------
__global__ __launch_bounds__(256) void k_softmax(const float* __restrict__ E) {
    const int n = blockIdx.x;
    const int tid = threadIdx.x;
    __shared__ float s_e[EMB];
    __shared__ float s_red[8];

    if (tid < EMB) s_e[tid] = E[n * EMB + tid];
    __syncthreads();
    float er[EMB];
#pragma unroll
    for (int d = 0; d < EMB; d++) er[d] = s_e[d];

    float vals[16];
    float vmax = 0.f;
#pragma unroll
    for (int j = 0; j < 16; j++) {
        const int m = tid + j * 256;
        const float* em = E + m * EMB;
        float dot = 0.f;
#pragma unroll
        for (int d = 0; d < EMB; d++) dot = fmaf(er[d], __ldg(em + d), dot);
        dot = fmaxf(dot, 0.f);
        vals[j] = dot;
        vmax = fmaxf(vmax, dot);
    }
#pragma unroll
    for (int o = 16; o; o >>= 1) vmax = fmaxf(vmax, __shfl_xor_sync(0xffffffffu, vmax, o));
    if ((tid & 31) == 0) s_red[tid >> 5] = vmax;
    __syncthreads();
    vmax = s_red[0];
#pragma unroll
    for (int w = 1; w < 8; w++) vmax = fmaxf(vmax, s_red[w]);

    float ssum = 0.f;
#pragma unroll
    for (int j = 0; j < 16; j++) {
        vals[j] = __expf(vals[j] - vmax);
        ssum += vals[j];
    }
#pragma unroll
    for (int o = 16; o; o >>= 1) ssum += __shfl_xor_sync(0xffffffffu, ssum, o);
    __syncthreads();
    if ((tid & 31) == 0) s_red[tid >> 5] = ssum;
    __syncthreads();
    ssum = 0.f;
#pragma unroll
    for (int w = 0; w < 8; w++) ssum += s_red[w];
    const float inv = 1.0f / ssum;

#pragma unroll
    for (int j = 0; j < 16; j++) {
        const float v = vals[j] * inv;
        const __half h = __float2half(v);
        const float r = v - __half2float(h);
        const size_t idx = (size_t)n * N_NODES + tid + j * 256;
        g_Ah[idx] = h;
        g_Al[idx] = __float2half(r);
    }
}

// ---------------------------------------------------------------------------
// Kernel 2: transpose x[b][m][c] -> X^T[j=b*64+c][m] as single fp16.
// ---------------------------------------------------------------------------
__global__ __launch_bounds__(256) void k_transpose(const float* __restrict__ x) {
    const int b = blockIdx.y;
    const int m0 = blockIdx.x * 64;
    const int tid = threadIdx.x;
    __shared__ float tile[64][65];

#pragma unroll
    for (int i = 0; i < 16; i++) {
        const int idx = tid + i * 256;
        const int mi = idx >> 6, c = idx & 63;
        tile[mi][c] = x[((size_t)b * N_NODES + m0 + mi) * CI + c];
    }
    __syncthreads();
#pragma unroll
    for (int i = 0; i < 16; i++) {
        const int idx = tid + i * 256;
        const int c = idx >> 6, mm = idx & 63;
        g_Xh[(size_t)(b * 64 + c) * N_NODES + m0 + mm] = __float2half(tile[mm][c]);
    }
}

// ---------------------------------------------------------------------------
// Kernel 3: y1 = A @ X via mma.sync fp16 2-product split precision.
// D[n, j] = (Ah + Al) * Xh   (fp32 accumulate)
// CTA tile 128x128, K-chunk 32, 2-stage cp.async, 8 warps (4Mx2N), warp 32x64.
// ---------------------------------------------------------------------------
#define KC 32
#define ROWB 80                       // padded row: 40 fp16 = 80B (conflict-free LDSM)
#define TILE_B (128 * ROWB)           // 10240 B
#define STAGE_B (3 * TILE_B)          // Ah, Al, Xh
#define SMEM_MMA (2 * STAGE_B)        // 61440 B
#define NT (N_NODES / KC)             // 128 chunks

__global__ __launch_bounds__(256, 2) void k_mma() {
    extern __shared__ __align__(128) char smem[];
    const uint32_t sb = smem_u32(smem);
    const int tid = threadIdx.x;
    const int wid = tid >> 5;
    const int lane = tid & 31;
    const int wm = wid >> 1;          // 0..3  (M: 32 rows each)
    const int wn = wid & 1;           // 0..1  (N: 64 cols each)
    const int n0 = blockIdx.y * 128;
    const int j0 = blockIdx.x * 128;

    // global load assignment: 2 segments of 16B per tile per thread
    int grow[2], gseg[2];
    uint32_t sdst[2];
#pragma unroll
    for (int i = 0; i < 2; i++) {
        const int s = tid + i * 256;      // 0..511
        grow[i] = s >> 2;                 // 0..127
        gseg[i] = s & 3;                  // 16B segment within 64B row
        sdst[i] = (uint32_t)(grow[i] * ROWB + gseg[i] * 16);
    }

    // ldmatrix source offsets (within a tile)
    uint32_t offA[2], offB[4];
#pragma unroll
    for (int mb = 0; mb < 2; mb++)
        offA[mb] = (uint32_t)((wm * 32 + mb * 16 + (lane & 15)) * ROWB + (lane >> 4) * 16);
#pragma unroll
    for (int nb = 0; nb < 4; nb++)
        offB[nb] = (uint32_t)((wn * 64 + nb * 16 + (lane & 15)) * ROWB + (lane >> 4) * 16);

    float acc[2][8][4];
#pragma unroll
    for (int mb = 0; mb < 2; mb++)
#pragma unroll
        for (int nb = 0; nb < 8; nb++)
#pragma unroll
            for (int q = 0; q < 4; q++) acc[mb][nb][q] = 0.f;

    // prologue: chunk 0 -> stage 0
    {
        const uint32_t st = sb;
#pragma unroll
        for (int i = 0; i < 2; i++) {
            const size_t ga = (size_t)(n0 + grow[i]) * N_NODES + gseg[i] * 8;
            const size_t gb = (size_t)(j0 + grow[i]) * N_NODES + gseg[i] * 8;
            cp_async16(st + 0 * TILE_B + sdst[i], g_Ah + ga);
            cp_async16(st + 1 * TILE_B + sdst[i], g_Al + ga);
            cp_async16(st + 2 * TILE_B + sdst[i], g_Xh + gb);
        }
        CP_COMMIT();
    }

    for (int t = 0; t < NT; t++) {
        const int s = t & 1;
        if (t + 1 < NT) {
            const uint32_t st = sb + (s ^ 1) * STAGE_B;
            const int m0 = (t + 1) * KC;
#pragma unroll
            for (int i = 0; i < 2; i++) {
                const size_t ga = (size_t)(n0 + grow[i]) * N_NODES + m0 + gseg[i] * 8;
                const size_t gb = (size_t)(j0 + grow[i]) * N_NODES + m0 + gseg[i] * 8;
                cp_async16(st + 0 * TILE_B + sdst[i], g_Ah + ga);
                cp_async16(st + 1 * TILE_B + sdst[i], g_Al + ga);
                cp_async16(st + 2 * TILE_B + sdst[i], g_Xh + gb);
            }
            CP_COMMIT();
            CP_WAIT(1);
        } else {
            CP_WAIT(0);
        }
        __syncthreads();

        const uint32_t st = sb + s * STAGE_B;
        const uint32_t bAh = st, bAl = st + TILE_B, bBh = st + 2 * TILE_B;
#pragma unroll
        for (int ks = 0; ks < 2; ks++) {
            const uint32_t ko = ks * 32;   // 16 fp16 = 32 bytes
            uint32_t ah[2][4], al[2][4];
#pragma unroll
            for (int mb = 0; mb < 2; mb++) {
                ldsm4(ah[mb], bAh + offA[mb] + ko);
                ldsm4(al[mb], bAl + offA[mb] + ko);
            }
#pragma unroll
            for (int nb = 0; nb < 4; nb++) {
                uint32_t bh[4];
                ldsm4(bh, bBh + offB[nb] + ko);
#pragma unroll
                for (int mb = 0; mb < 2; mb++) {
                    float* c0 = acc[mb][nb * 2 + 0];
                    float* c1 = acc[mb][nb * 2 + 1];
                    mma_f16(c0, ah[mb], bh[0], bh[2]);
                    mma_f16(c0, al[mb], bh[0], bh[2]);
                    mma_f16(c1, ah[mb], bh[1], bh[3]);
                    mma_f16(c1, al[mb], bh[1], bh[3]);
                }
            }
        }
        __syncthreads();
    }

    // epilogue: write y1[b][n][c]; each warp's 64-col span lies in ONE batch b.
    const int jw = j0 + wn * 64;
    const int b = jw >> 6;
#pragma unroll
    for (int mb = 0; mb < 2; mb++) {
        const int nrow = n0 + wm * 32 + mb * 16 + (lane >> 2);
#pragma unroll
        for (int nb = 0; nb < 8; nb++) {
            const int c = nb * 8 + (lane & 3) * 2;
            float* d0 = &g_y1[((size_t)b * N_NODES + nrow) * CI + c];
            float* d1 = &g_y1[((size_t)b * N_NODES + nrow + 8) * CI + c];
            float2 v0 = {acc[mb][nb][0], acc[mb][nb][1]};
            float2 v1 = {acc[mb][nb][2], acc[mb][nb][3]};
            *(float2*)d0 = v0;
            *(float2*)d1 = v1;
        }
    }
}

// ---------------------------------------------------------------------------
// Kernel 4: per-node weights + final per-node GEMM, 4-batch register blocking.
// Thread (og, bq): outputs o = og*4..+3 for batches b = bq*4..+3.
// All 64 batches resident; x/y stored transposed [i][b] (pad 68) for float4.
// ---------------------------------------------------------------------------
#define SXT_OFF  8192                 // floats: sW occupies [0, 8192)
#define SYT_OFF  (SXT_OFF + 64 * 68)
#define SB_OFF   (SYT_OFF + 64 * 68)
#define SE_OFF   (SB_OFF + 64)
#define KOUT_SMEM ((SE_OFF + 16) * 4)

__global__ __launch_bounds__(256) void k_out(const float* __restrict__ E,
                                             const float* __restrict__ Wp,
                                             const float* __restrict__ bp,
                                             const float* __restrict__ x,
                                             float* __restrict__ out) {
    extern __shared__ float dsm[];
    const int n = blockIdx.x;
    const int tid = threadIdx.x;

    if (tid < EMB) dsm[SE_OFF + tid] = E[n * EMB + tid];
    __syncthreads();
    float e[EMB];
#pragma unroll
    for (int d = 0; d < EMB; d++) e[d] = dsm[SE_OFF + d];

    // W[k,i,o] = sum_d e[d] * Wp[d,k,i,o]
#pragma unroll 8
    for (int u = 0; u < 32; u++) {
        const int idx = tid + u * 256;
        float acc = 0.f;
#pragma unroll
        for (int d = 0; d < EMB; d++) acc = fmaf(e[d], __ldg(Wp + d * 8192 + idx), acc);
        dsm[idx] = acc;
    }
    if (tid < 64) {
        float acc = 0.f;
#pragma unroll
        for (int d = 0; d < EMB; d++) acc = fmaf(e[d], bp[d * 64 + tid], acc);
        dsm[SB_OFF + tid] = acc;
    }

    // fill transposed x/y: [i][b] with row pad 68
#pragma unroll
    for (int u = 0; u < 16; u++) {
        const int idx = tid + u * 256;
        const int b = idx >> 6, i = idx & 63;
        dsm[SXT_OFF + i * 68 + b] = x[((size_t)b * N_NODES + n) * CI + i];
        dsm[SYT_OFF + i * 68 + b] = g_y1[((size_t)b * N_NODES + n) * CI + i];
    }
    __syncthreads();

    const int og = tid & 15;
    const int bq = tid >> 4;

    float acc[4][4];
    const float4 bias = *(const float4*)&dsm[SB_OFF + og * 4];
#pragma unroll
    for (int bb = 0; bb < 4; bb++) {
        acc[bb][0] = bias.x; acc[bb][1] = bias.y; acc[bb][2] = bias.z; acc[bb][3] = bias.w;
    }

#pragma unroll 8
    for (int i = 0; i < 64; i++) {
        const float4 w0 = *(const float4*)&dsm[i * 64 + og * 4];          // sW[0][i][og*4]
        const float4 w1 = *(const float4*)&dsm[4096 + i * 64 + og * 4];   // sW[1][i][og*4]
        const float4 xv = *(const float4*)&dsm[SXT_OFF + i * 68 + bq * 4];
        const float4 yv = *(const float4*)&dsm[SYT_OFF + i * 68 + bq * 4];
        const float xr[4] = {xv.x, xv.y, xv.z, xv.w};
        const float yr[4] = {yv.x, yv.y, yv.z, yv.w};
#pragma unroll
        for (int bb = 0; bb < 4; bb++) {
            acc[bb][0] = fmaf(xr[bb], w0.x, fmaf(yr[bb], w1.x, acc[bb][0]));
            acc[bb][1] = fmaf(xr[bb], w0.y, fmaf(yr[bb], w1.y, acc[bb][1]));
            acc[bb][2] = fmaf(xr[bb], w0.z, fmaf(yr[bb], w1.z, acc[bb][2]));
            acc[bb][3] = fmaf(xr[bb], w0.w, fmaf(yr[bb], w1.w, acc[bb][3]));
        }
    }

#pragma unroll
    for (int bb = 0; bb < 4; bb++) {
        float4 v = {acc[bb][0], acc[bb][1], acc[bb][2], acc[bb][3]};
        *(float4*)&out[((size_t)(bq * 4 + bb) * N_NODES + n) * CO + og * 4] = v;
    }
}

// ---------------------------------------------------------------------------
extern "C" void kernel_launch(void* const* d_in, const int* in_sizes, int n_in,
                              void* d_out, int out_size) {
    const float* x  = (const float*)d_in[0];
    const float* E  = (const float*)d_in[1];
    const float* Wp = (const float*)d_in[2];
    const float* bp = (const float*)d_in[3];
    float* out = (float*)d_out;

    cudaFuncSetAttribute(k_mma, cudaFuncAttributeMaxDynamicSharedMemorySize, SMEM_MMA);
    cudaFuncSetAttribute(k_out, cudaFuncAttributeMaxDynamicSharedMemorySize, KOUT_SMEM);

    k_softmax<<<N_NODES, 256>>>(E);
    dim3 gT(N_NODES / 64, NBATCH);
    k_transpose<<<gT, 256>>>(x);
    dim3 gM(N_NODES / 128, N_NODES / 128);
    k_mma<<<gM, 256, SMEM_MMA>>>();
    k_out<<<N_NODES, 256, KOUT_SMEM>>>(E, Wp, bp, x, out);
}

// round 7
// speedup vs baseline: 4.4601x; 1.6385x over previous
#include <cuda_runtime.h>
#include <cuda_fp16.h>
#include <cstdint>

#define N_NODES 4096
#define EMB 10
#define NBATCH 64
#define CI 64
#define CO 64

// ---------------- device scratch (allocation-free rule) --------------------
__device__ __half g_Ah[(size_t)N_NODES * N_NODES];   // softmax(relu(EE^T)) fp16
__device__ __half g_Xh[(size_t)N_NODES * N_NODES];   // X^T[j=b*64+c][m] fp16
__device__ float g_y1[(size_t)NBATCH * N_NODES * CI];// diffusion result [b][n][c]

// ---------------- PTX helpers ---------------------------------------------
__device__ __forceinline__ uint32_t smem_u32(const void* p) {
    uint32_t a;
    asm("{ .reg .u64 t; cvta.to.shared.u64 t, %1; cvt.u32.u64 %0, t; }" : "=r"(a) : "l"(p));
    return a;
}
__device__ __forceinline__ void cp_async16(uint32_t dst, const void* src) {
    asm volatile("cp.async.cg.shared.global [%0], [%1], 16;" :: "r"(dst), "l"(src));
}
#define CP_COMMIT()  asm volatile("cp.async.commit_group;" ::: "memory")
#define CP_WAIT(N)   asm volatile("cp.async.wait_group %0;" :: "n"(N) : "memory")

__device__ __forceinline__ void ldsm4(uint32_t* r, uint32_t addr) {
    asm volatile("ldmatrix.sync.aligned.m8n8.x4.shared.b16 {%0,%1,%2,%3}, [%4];"
        : "=r"(r[0]), "=r"(r[1]), "=r"(r[2]), "=r"(r[3]) : "r"(addr));
}
__device__ __forceinline__ void mma_f16(float* c, const uint32_t* a,
                                        uint32_t b0, uint32_t b1) {
    asm volatile("mma.sync.aligned.m16n8k16.row.col.f32.f16.f16.f32 "
        "{%0,%1,%2,%3}, {%4,%5,%6,%7}, {%8,%9}, {%0,%1,%2,%3};"
        : "+f"(c[0]), "+f"(c[1]), "+f"(c[2]), "+f"(c[3])
        : "r"(a[0]), "r"(a[1]), "r"(a[2]), "r"(a[3]), "r"(b0), "r"(b1));
}

// ---------------------------------------------------------------------------
// Kernel 1: per-row softmax of relu(E E^T) -> fp16.
// ---------------------------------------------------------------------------
__global__ __launch_bounds__(256) void k_softmax(const float* __restrict__ E) {
    const int n = blockIdx.x;
    const int tid = threadIdx.x;
    __shared__ float s_e[EMB];
    __shared__ float s_red[8];

    if (tid < EMB) s_e[tid] = E[n * EMB + tid];
    __syncthreads();
    float er[EMB];
#pragma unroll
    for (int d = 0; d < EMB; d++) er[d] = s_e[d];

    float vals[16];
    float vmax = 0.f;
#pragma unroll
    for (int j = 0; j < 16; j++) {
        const int m = tid + j * 256;
        const float* em = E + m * EMB;
        float dot = 0.f;
#pragma unroll
        for (int d = 0; d < EMB; d++) dot = fmaf(er[d], __ldg(em + d), dot);
        dot = fmaxf(dot, 0.f);
        vals[j] = dot;
        vmax = fmaxf(vmax, dot);
    }
#pragma unroll
    for (int o = 16; o; o >>= 1) vmax = fmaxf(vmax, __shfl_xor_sync(0xffffffffu, vmax, o));
    if ((tid & 31) == 0) s_red[tid >> 5] = vmax;
    __syncthreads();
    vmax = s_red[0];
#pragma unroll
    for (int w = 1; w < 8; w++) vmax = fmaxf(vmax, s_red[w]);

    float ssum = 0.f;
#pragma unroll
    for (int j = 0; j < 16; j++) {
        vals[j] = __expf(vals[j] - vmax);
        ssum += vals[j];
    }
#pragma unroll
    for (int o = 16; o; o >>= 1) ssum += __shfl_xor_sync(0xffffffffu, ssum, o);
    __syncthreads();
    if ((tid & 31) == 0) s_red[tid >> 5] = ssum;
    __syncthreads();
    ssum = 0.f;
#pragma unroll
    for (int w = 0; w < 8; w++) ssum += s_red[w];
    const float inv = 1.0f / ssum;

#pragma unroll
    for (int j = 0; j < 16; j++)
        g_Ah[(size_t)n * N_NODES + tid + j * 256] = __float2half(vals[j] * inv);
}

// ---------------------------------------------------------------------------
// Kernel 2: transpose x[b][m][c] -> X^T[j=b*64+c][m] fp16.
// ---------------------------------------------------------------------------
__global__ __launch_bounds__(256) void k_transpose(const float* __restrict__ x) {
    const int b = blockIdx.y;
    const int m0 = blockIdx.x * 64;
    const int tid = threadIdx.x;
    __shared__ float tile[64][65];

#pragma unroll
    for (int i = 0; i < 16; i++) {
        const int idx = tid + i * 256;
        const int mi = idx >> 6, c = idx & 63;
        tile[mi][c] = x[((size_t)b * N_NODES + m0 + mi) * CI + c];
    }
    __syncthreads();
#pragma unroll
    for (int i = 0; i < 16; i++) {
        const int idx = tid + i * 256;
        const int c = idx >> 6, mm = idx & 63;
        g_Xh[(size_t)(b * 64 + c) * N_NODES + m0 + mm] = __float2half(tile[mm][c]);
    }
}

// ---------------------------------------------------------------------------
// Kernel 3: y1 = A @ X via mma.sync fp16 single product, fp32 accumulate.
// CTA tile 128x128, K-chunk 64, 2-stage cp.async, 8 warps (4Mx2N), warp 32x64.
// Row pad 144B: bank walk 36%32=4 per row -> conflict-free ldmatrix.
// ---------------------------------------------------------------------------
#define KC 64
#define ROWB 144                      // 64 fp16 = 128B data + 16B pad
#define TILE_B (128 * ROWB)           // 18432 B
#define STAGE_B (2 * TILE_B)          // Ah, Xh
#define SMEM_MMA (2 * STAGE_B)        // 73728 B
#define NT (N_NODES / KC)             // 64 chunks

__global__ __launch_bounds__(256, 2) void k_mma() {
    extern __shared__ __align__(128) char smem[];
    const uint32_t sb = smem_u32(smem);
    const int tid = threadIdx.x;
    const int wid = tid >> 5;
    const int lane = tid & 31;
    const int wm = wid >> 1;          // 0..3  (M: 32 rows each)
    const int wn = wid & 1;           // 0..1  (N: 64 cols each)
    const int n0 = blockIdx.y * 128;
    const int j0 = blockIdx.x * 128;

    // global load assignment: 4 x 16B segments per tile per thread
    int grow[4], gseg[4];
    uint32_t sdst[4];
#pragma unroll
    for (int i = 0; i < 4; i++) {
        const int s = tid + i * 256;      // 0..1023
        grow[i] = s >> 3;                 // 0..127
        gseg[i] = s & 7;                  // 16B segment within 128B row
        sdst[i] = (uint32_t)(grow[i] * ROWB + gseg[i] * 16);
    }

    // ldmatrix source offsets (within a tile)
    uint32_t offA[2], offB[4];
#pragma unroll
    for (int mb = 0; mb < 2; mb++)
        offA[mb] = (uint32_t)((wm * 32 + mb * 16 + (lane & 15)) * ROWB + (lane >> 4) * 16);
#pragma unroll
    for (int nb = 0; nb < 4; nb++)
        offB[nb] = (uint32_t)((wn * 64 + nb * 16 + (lane & 15)) * ROWB + (lane >> 4) * 16);

    float acc[2][8][4];
#pragma unroll
    for (int mb = 0; mb < 2; mb++)
#pragma unroll
        for (int nb = 0; nb < 8; nb++)
#pragma unroll
            for (int q = 0; q < 4; q++) acc[mb][nb][q] = 0.f;

    // prologue: chunk 0 -> stage 0
    {
        const uint32_t st = sb;
#pragma unroll
        for (int i = 0; i < 4; i++) {
            cp_async16(st + sdst[i],          g_Ah + (size_t)(n0 + grow[i]) * N_NODES + gseg[i] * 8);
            cp_async16(st + TILE_B + sdst[i], g_Xh + (size_t)(j0 + grow[i]) * N_NODES + gseg[i] * 8);
        }
        CP_COMMIT();
    }

    for (int t = 0; t < NT; t++) {
        const int s = t & 1;
        if (t + 1 < NT) {
            const uint32_t st = sb + (s ^ 1) * STAGE_B;
            const int m0 = (t + 1) * KC;
#pragma unroll
            for (int i = 0; i < 4; i++) {
                cp_async16(st + sdst[i],          g_Ah + (size_t)(n0 + grow[i]) * N_NODES + m0 + gseg[i] * 8);
                cp_async16(st + TILE_B + sdst[i], g_Xh + (size_t)(j0 + grow[i]) * N_NODES + m0 + gseg[i] * 8);
            }
            CP_COMMIT();
            CP_WAIT(1);
        } else {
            CP_WAIT(0);
        }
        __syncthreads();

        const uint32_t bA = sb + s * STAGE_B;
        const uint32_t bB = bA + TILE_B;
#pragma unroll
        for (int ks = 0; ks < 4; ks++) {
            const uint32_t ko = ks * 32;   // 16 fp16 = 32 bytes
            uint32_t ah[2][4];
#pragma unroll
            for (int mb = 0; mb < 2; mb++) ldsm4(ah[mb], bA + offA[mb] + ko);
#pragma unroll
            for (int nb = 0; nb < 4; nb++) {
                uint32_t bh[4];
                ldsm4(bh, bB + offB[nb] + ko);
#pragma unroll
                for (int mb = 0; mb < 2; mb++) {
                    mma_f16(acc[mb][nb * 2 + 0], ah[mb], bh[0], bh[2]);
                    mma_f16(acc[mb][nb * 2 + 1], ah[mb], bh[1], bh[3]);
                }
            }
        }
        __syncthreads();
    }

    // epilogue: write y1[b][n][c]; each warp's 64-col span lies in ONE batch b.
    const int jw = j0 + wn * 64;
    const int b = jw >> 6;
#pragma unroll
    for (int mb = 0; mb < 2; mb++) {
        const int nrow = n0 + wm * 32 + mb * 16 + (lane >> 2);
#pragma unroll
        for (int nb = 0; nb < 8; nb++) {
            const int c = nb * 8 + (lane & 3) * 2;
            float* d0 = &g_y1[((size_t)b * N_NODES + nrow) * CI + c];
            float* d1 = &g_y1[((size_t)b * N_NODES + nrow + 8) * CI + c];
            float2 v0 = {acc[mb][nb][0], acc[mb][nb][1]};
            float2 v1 = {acc[mb][nb][2], acc[mb][nb][3]};
            *(float2*)d0 = v0;
            *(float2*)d1 = v1;
        }
    }
}

// ---------------------------------------------------------------------------
// Kernel 4: per-node weights + final per-node GEMM, 4-batch register blocking.
// ---------------------------------------------------------------------------
#define SXT_OFF  8192                 // floats: sW occupies [0, 8192)
#define SYT_OFF  (SXT_OFF + 64 * 68)
#define SB_OFF   (SYT_OFF + 64 * 68)
#define SE_OFF   (SB_OFF + 64)
#define KOUT_SMEM ((SE_OFF + 16) * 4)

__global__ __launch_bounds__(256) void k_out(const float* __restrict__ E,
                                             const float* __restrict__ Wp,
                                             const float* __restrict__ bp,
                                             const float* __restrict__ x,
                                             float* __restrict__ out) {
    extern __shared__ float dsm[];
    const int n = blockIdx.x;
    const int tid = threadIdx.x;

    if (tid < EMB) dsm[SE_OFF + tid] = E[n * EMB + tid];
    __syncthreads();
    float e[EMB];
#pragma unroll
    for (int d = 0; d < EMB; d++) e[d] = dsm[SE_OFF + d];

#pragma unroll 8
    for (int u = 0; u < 32; u++) {
        const int idx = tid + u * 256;
        float acc = 0.f;
#pragma unroll
        for (int d = 0; d < EMB; d++) acc = fmaf(e[d], __ldg(Wp + d * 8192 + idx), acc);
        dsm[idx] = acc;
    }
    if (tid < 64) {
        float acc = 0.f;
#pragma unroll
        for (int d = 0; d < EMB; d++) acc = fmaf(e[d], bp[d * 64 + tid], acc);
        dsm[SB_OFF + tid] = acc;
    }

#pragma unroll
    for (int u = 0; u < 16; u++) {
        const int idx = tid + u * 256;
        const int b = idx >> 6, i = idx & 63;
        dsm[SXT_OFF + i * 68 + b] = x[((size_t)b * N_NODES + n) * CI + i];
        dsm[SYT_OFF + i * 68 + b] = g_y1[((size_t)b * N_NODES + n) * CI + i];
    }
    __syncthreads();

    const int og = tid & 15;
    const int bq = tid >> 4;

    float acc[4][4];
    const float4 bias = *(const float4*)&dsm[SB_OFF + og * 4];
#pragma unroll
    for (int bb = 0; bb < 4; bb++) {
        acc[bb][0] = bias.x; acc[bb][1] = bias.y; acc[bb][2] = bias.z; acc[bb][3] = bias.w;
    }

#pragma unroll 8
    for (int i = 0; i < 64; i++) {
        const float4 w0 = *(const float4*)&dsm[i * 64 + og * 4];
        const float4 w1 = *(const float4*)&dsm[4096 + i * 64 + og * 4];
        const float4 xv = *(const float4*)&dsm[SXT_OFF + i * 68 + bq * 4];
        const float4 yv = *(const float4*)&dsm[SYT_OFF + i * 68 + bq * 4];
        const float xr[4] = {xv.x, xv.y, xv.z, xv.w};
        const float yr[4] = {yv.x, yv.y, yv.z, yv.w};
#pragma unroll
        for (int bb = 0; bb < 4; bb++) {
            acc[bb][0] = fmaf(xr[bb], w0.x, fmaf(yr[bb], w1.x, acc[bb][0]));
            acc[bb][1] = fmaf(xr[bb], w0.y, fmaf(yr[bb], w1.y, acc[bb][1]));
            acc[bb][2] = fmaf(xr[bb], w0.z, fmaf(yr[bb], w1.z, acc[bb][2]));
            acc[bb][3] = fmaf(xr[bb], w0.w, fmaf(yr[bb], w1.w, acc[bb][3]));
        }
    }

#pragma unroll
    for (int bb = 0; bb < 4; bb++) {
        float4 v = {acc[bb][0], acc[bb][1], acc[bb][2], acc[bb][3]};
        *(float4*)&out[((size_t)(bq * 4 + bb) * N_NODES + n) * CO + og * 4] = v;
    }
}

// ---------------------------------------------------------------------------
extern "C" void kernel_launch(void* const* d_in, const int* in_sizes, int n_in,
                              void* d_out, int out_size) {
    const float* x  = (const float*)d_in[0];
    const float* E  = (const float*)d_in[1];
    const float* Wp = (const float*)d_in[2];
    const float* bp = (const float*)d_in[3];
    float* out = (float*)d_out;

    cudaFuncSetAttribute(k_mma, cudaFuncAttributeMaxDynamicSharedMemorySize, SMEM_MMA);
    cudaFuncSetAttribute(k_out, cudaFuncAttributeMaxDynamicSharedMemorySize, KOUT_SMEM);

    k_softmax<<<N_NODES, 256>>>(E);
    dim3 gT(N_NODES / 64, NBATCH);
    k_transpose<<<gT, 256>>>(x);
    dim3 gM(N_NODES / 128, N_NODES / 128);
    k_mma<<<gM, 256, SMEM_MMA>>>();
    k_out<<<N_NODES, 256, KOUT_SMEM>>>(E, Wp, bp, x, out);
}